// round 15
// baseline (speedup 1.0000x reference)
#include <cuda_runtime.h>
#include <cuda_fp16.h>
#include <cstdint>

#define DIM 256
#define HEADS 8
#define HD 32
#define N_TOK 64
#define IMG 256
#define BATCH 4
#define NWIN 1024
#define NPIX 262144
#define SCALE 0.17677669529663687f

// scratch (static device globals: allocation-free per harness rules)
__device__ __align__(256) __half g_o[67108864];     // attn output (fp16, pre-rounded)
__device__ __align__(256) __half g_wq[196608];      // fp16 qkv_w
__device__ __align__(256) __half g_wp[65536];       // fp16 proj_w

extern __shared__ float dynsmem[];

__device__ __forceinline__ uint32_t pack_h2(float a, float b) {
    __half2 h = __floats2half2_rn(a, b);
    uint32_t r;
    memcpy(&r, &h, 4);
    return r;
}

__device__ __forceinline__ void mma_f16(float c[4], const uint32_t a[4],
                                        uint32_t b0, uint32_t b1) {
    asm volatile(
        "mma.sync.aligned.m16n8k16.row.col.f32.f16.f16.f32 "
        "{%0,%1,%2,%3}, {%4,%5,%6,%7}, {%8,%9}, {%0,%1,%2,%3};"
        : "+f"(c[0]), "+f"(c[1]), "+f"(c[2]), "+f"(c[3])
        : "r"(a[0]), "r"(a[1]), "r"(a[2]), "r"(a[3]), "r"(b0), "r"(b1));
}

__device__ __forceinline__ uint32_t smem_u32(const void* p) {
    uint32_t a;
    asm("{ .reg .u64 t; cvta.to.shared.u64 t, %1; cvt.u32.u64 %0, t; }"
        : "=r"(a) : "l"(p));
    return a;
}

#define LDSM_X4(R0, R1, R2, R3, ADDR) \
    asm volatile("ldmatrix.sync.aligned.m8n8.x4.shared.b16 {%0,%1,%2,%3}, [%4];" \
                 : "=r"(R0), "=r"(R1), "=r"(R2), "=r"(R3) : "r"(ADDR))

#define LDSM_X4_TRANS(R0, R1, R2, R3, ADDR) \
    asm volatile("ldmatrix.sync.aligned.m8n8.x4.trans.shared.b16 {%0,%1,%2,%3}, [%4];" \
                 : "=r"(R0), "=r"(R1), "=r"(R2), "=r"(R3) : "r"(ADDR))

#define CP_ASYNC16(dst_u32, src) \
    asm volatile("cp.async.cg.shared.global [%0], [%1], 16;" \
                 :: "r"(dst_u32), "l"(src) : "memory")
#define CP_COMMIT() asm volatile("cp.async.commit_group;" ::: "memory")
#define CP_WAIT(n)  asm volatile("cp.async.wait_group %0;" :: "n"(n) : "memory")

// ---------------------------------------------------------------------------
// fp32 -> fp16 rounding pass (weights only)
// ---------------------------------------------------------------------------
__global__ __launch_bounds__(256) void round_kernel(const float4* __restrict__ in,
                                                    uint4* __restrict__ out, int n8) {
    int i = blockIdx.x * 256 + threadIdx.x;
    if (i < n8) {
        float4 v0 = in[i * 2], v1 = in[i * 2 + 1];
        uint4 r;
        r.x = pack_h2(v0.x, v0.y);
        r.y = pack_h2(v0.z, v0.w);
        r.z = pack_h2(v1.x, v1.y);
        r.w = pack_h2(v1.z, v1.w);
        out[i] = r;
    }
}

// ---------------------------------------------------------------------------
// FUSED qkv-projection + shifted-window attention. 1 block per window,
// 256 thr, warp = head. Eliminates the 805 MB g_qkv round-trip.
//
// smem (halves): xs[8 kstages][64][40]          @ 0      (20480)
//                wbuf[8 warps][3 bufs][32][40]  @ 20480  (30720)
//                heads[8][Q 2560|K 2560|V 2560] @ 51200  (61440)
// total 112640 halves = 225280 B -> 1 CTA/SM, 8 desynced warps.
//
// Phase 1 (block): load x rows of this window's 64 tokens (shift folded in),
//                  fp32->fp16 cvt, STS into xs. One __syncthreads.
// Phase 2 (warp):  3 passes (q,k,v): stream own head's 32 W rows per pass via
//                  3-buffer cp.async ring; M=64xN=32xK=256 via proven
//                  LDSM/HMMA path; epilogue STS into own head's Q/K/V block.
// Phase 3 (warp):  R14 attention verbatim (ldmatrix frags, smem P, analytic
//                  mask, register softmax); store fuses unpartition+roll(-4).
// ---------------------------------------------------------------------------
__global__ __launch_bounds__(256, 1) void fused_qkv_attn(
    const float* __restrict__ x, const __half* __restrict__ Wq) {
    __shared__ int sReg[64];
    __half* smemh = (__half*)dynsmem;

    const int win = blockIdx.x;
    const int wl = win & 1023;
    const int b = win >> 10;
    const int tid = threadIdx.x;
    const int wid = tid >> 5, lane = tid & 31;
    const int g = lane >> 2, tig = lane & 3;

    // ---- Phase 1: x tile (64 tokens x 256 ch), shift + fp16 cvt ----
#pragma unroll
    for (int it = 0; it < 8; ++it) {
        int idx = tid + it * 256;            // 0..2047
        int tok = idx >> 5, c8 = idx & 31;
        int hs = ((wl >> 5) << 3) + (tok >> 3);
        int ws = ((wl & 31) << 3) + (tok & 7);
        int h = (hs + 252) & 255;
        int w = (ws + 252) & 255;
        const float* src = x + (((size_t)b * IMG + h) * IMG + w) * DIM + c8 * 8;
        float4 v0 = *(const float4*)src;
        float4 v1 = *(const float4*)(src + 4);
        uint4 u = make_uint4(pack_h2(v0.x, v0.y), pack_h2(v0.z, v0.w),
                             pack_h2(v1.x, v1.y), pack_h2(v1.z, v1.w));
        int stage = c8 >> 2, part = c8 & 3;
        *(uint4*)(smemh + stage * 2560 + tok * 40 + part * 8) = u;
    }
    if (tid < 64) {
        int hs = ((wl >> 5) << 3) + (tid >> 3);
        int ws = ((wl & 31) << 3) + (tid & 7);
        int rh = (hs < 248) ? 0 : (hs < 252 ? 1 : 2);
        int rw = (ws < 248) ? 0 : (ws < 252 ? 1 : 2);
        sReg[tid] = rh * 3 + rw;
    }
    __syncthreads();

    const uint32_t xs_u = smem_u32(smemh);
    const uint32_t wb_u = smem_u32(smemh + 20480 + wid * 3840);
    const uint32_t headBase = smem_u32(smemh + 51200 + wid * 7680);
    __half* headSec = smemh + 51200 + wid * 7680;

    const uint32_t a_lane40 = (uint32_t)((lane & 15) * 40 + (lane >> 4) * 8) * 2u;
    const uint32_t bLaneOff = (uint32_t)(lane * 40) * 2u;

    // ---- Phase 2: per-warp qkv GEMM (3 passes) ----
#pragma unroll 1
    for (int pass = 0; pass < 3; ++pass) {
        float acc[4][4][4];
#pragma unroll
        for (int i = 0; i < 4; ++i)
#pragma unroll
            for (int j = 0; j < 4; ++j)
#pragma unroll
                for (int c = 0; c < 4; ++c) acc[i][j][c] = 0.f;

        const __half* wpass = Wq + (size_t)(pass * 256 + wid * 32) * DIM;
        auto issueW = [&](int s) {
#pragma unroll
            for (int j = 0; j < 4; ++j)
                CP_ASYNC16(wb_u + (uint32_t)((s % 3) * 1280 + lane * 40 + j * 8) * 2u,
                           wpass + (size_t)lane * DIM + s * 32 + j * 8);
            CP_COMMIT();
        };
        issueW(0);
        issueW(1);

#pragma unroll 1
        for (int s = 0; s < 8; ++s) {
            if (s < 7) { CP_WAIT(1); }
            else { CP_WAIT(0); }
            __syncwarp();
            if (s < 6) issueW(s + 2);

            const uint32_t aB = xs_u + (uint32_t)(s * 2560) * 2u + a_lane40;
            const uint32_t bB = wb_u + (uint32_t)((s % 3) * 1280) * 2u + bLaneOff;
#pragma unroll
            for (int kk = 0; kk < 2; ++kk) {
                uint32_t a[4][4];
#pragma unroll
                for (int mt = 0; mt < 4; ++mt)
                    LDSM_X4(a[mt][0], a[mt][1], a[mt][2], a[mt][3],
                            aB + (uint32_t)(mt * 16 * 40 + kk * 16) * 2u);
                uint32_t b0[4], b1[4];
                LDSM_X4(b0[0], b0[1], b0[2], b0[3], bB + (uint32_t)(kk * 16) * 2u);
                LDSM_X4(b1[0], b1[1], b1[2], b1[3],
                        bB + (uint32_t)(kk * 16 + 8) * 2u);
#pragma unroll
                for (int nt = 0; nt < 4; ++nt)
#pragma unroll
                    for (int mt = 0; mt < 4; ++mt)
                        mma_f16(acc[mt][nt], a[mt], b0[nt], b1[nt]);
            }
        }

        // epilogue: write this head's 32 channels of q/k/v for 64 tokens
        __half* dsec = headSec + pass * 2560;
#pragma unroll
        for (int mt = 0; mt < 4; ++mt)
#pragma unroll
            for (int e = 0; e < 2; ++e) {
                int row = mt * 16 + e * 8 + g;
#pragma unroll
                for (int nt = 0; nt < 4; ++nt) {
                    int col = nt * 8 + 2 * tig;
                    uint32_t p = pack_h2(acc[mt][nt][e * 2], acc[mt][nt][e * 2 + 1]);
                    *(uint32_t*)(dsec + row * 40 + col) = p;
                }
            }
    }
    __syncwarp();

    // ---- Phase 3: attention (R14 proven, per-warp) ----
    const uint32_t qBase = headBase + a_lane40;
    const uint32_t kBase = headBase + 2560u * 2u + bLaneOff;
    __half* hP = headSec;                    // P overlays Q,K after S phase

    float accS[4][8][4];
#pragma unroll
    for (int i = 0; i < 4; ++i)
#pragma unroll
        for (int j = 0; j < 8; ++j)
#pragma unroll
            for (int c = 0; c < 4; ++c) accS[i][j][c] = 0.f;

#pragma unroll
    for (int kk = 0; kk < 2; ++kk) {
        uint32_t a[4][4];
#pragma unroll
        for (int mt = 0; mt < 4; ++mt)
            LDSM_X4(a[mt][0], a[mt][1], a[mt][2], a[mt][3],
                    qBase + (uint32_t)(mt * 16 * 40 + kk * 16) * 2u);
        uint32_t b0[8], b1[8];
#pragma unroll
        for (int half = 0; half < 2; ++half) {
            const uint32_t hb = kBase + (uint32_t)(half * 32 * 40) * 2u;
            LDSM_X4(b0[half * 4 + 0], b0[half * 4 + 1], b0[half * 4 + 2],
                    b0[half * 4 + 3], hb + (uint32_t)(kk * 16) * 2u);
            LDSM_X4(b1[half * 4 + 0], b1[half * 4 + 1], b1[half * 4 + 2],
                    b1[half * 4 + 3], hb + (uint32_t)(kk * 16 + 8) * 2u);
        }
#pragma unroll
        for (int nt = 0; nt < 8; ++nt)
#pragma unroll
            for (int mt = 0; mt < 4; ++mt)
                mma_f16(accS[mt][nt], a[mt], b0[nt], b1[nt]);
    }

    const bool edge = ((wl >> 5) == 31) || ((wl & 31) == 31);
#pragma unroll
    for (int mt = 0; mt < 4; ++mt)
#pragma unroll
        for (int nt = 0; nt < 8; ++nt)
#pragma unroll
            for (int c = 0; c < 4; ++c) accS[mt][nt][c] *= SCALE;
    if (edge) {
        int creg[2][8];
#pragma unroll
        for (int nt = 0; nt < 8; ++nt) {
            creg[0][nt] = sReg[nt * 8 + 2 * tig];
            creg[1][nt] = sReg[nt * 8 + 2 * tig + 1];
        }
#pragma unroll
        for (int mt = 0; mt < 4; ++mt)
#pragma unroll
            for (int e = 0; e < 2; ++e) {
                int rr = sReg[mt * 16 + e * 8 + g];
#pragma unroll
                for (int nt = 0; nt < 8; ++nt) {
                    if (creg[0][nt] != rr) accS[mt][nt][e * 2] -= 100.f;
                    if (creg[1][nt] != rr) accS[mt][nt][e * 2 + 1] -= 100.f;
                }
            }
    }

    float inv[4][2];
#pragma unroll
    for (int mt = 0; mt < 4; ++mt) {
#pragma unroll
        for (int e = 0; e < 2; ++e) {
            float mx = -1e30f;
#pragma unroll
            for (int nt = 0; nt < 8; ++nt) {
                mx = fmaxf(mx, accS[mt][nt][e * 2]);
                mx = fmaxf(mx, accS[mt][nt][e * 2 + 1]);
            }
            mx = fmaxf(mx, __shfl_xor_sync(0xffffffffu, mx, 1));
            mx = fmaxf(mx, __shfl_xor_sync(0xffffffffu, mx, 2));
            float sum = 0.f;
#pragma unroll
            for (int nt = 0; nt < 8; ++nt) {
                float e0 = __expf(accS[mt][nt][e * 2] - mx);
                float e1 = __expf(accS[mt][nt][e * 2 + 1] - mx);
                accS[mt][nt][e * 2] = e0;
                accS[mt][nt][e * 2 + 1] = e1;
                sum += e0 + e1;
            }
            sum += __shfl_xor_sync(0xffffffffu, sum, 1);
            sum += __shfl_xor_sync(0xffffffffu, sum, 2);
            inv[mt][e] = 1.f / sum;
        }
    }

    __syncwarp();   // all Q/K reads done before P overlays them
#pragma unroll
    for (int mt = 0; mt < 4; ++mt)
#pragma unroll
        for (int e = 0; e < 2; ++e) {
            float iv = inv[mt][e];
            __half* prow = hP + (mt * 16 + e * 8 + g) * 72;
#pragma unroll
            for (int nt = 0; nt < 8; ++nt) {
                uint32_t p = pack_h2(accS[mt][nt][e * 2] * iv,
                                     accS[mt][nt][e * 2 + 1] * iv);
                *(uint32_t*)(prow + nt * 8 + 2 * tig) = p;
            }
        }
    __syncwarp();

    float accO[4][4][4];
#pragma unroll
    for (int i = 0; i < 4; ++i)
#pragma unroll
        for (int j = 0; j < 4; ++j)
#pragma unroll
            for (int c = 0; c < 4; ++c) accO[i][j][c] = 0.f;

    const uint32_t pBase =
        headBase + (uint32_t)((lane & 15) * 72 + (lane >> 4) * 8) * 2u;
    const int grp = lane >> 3, l8 = lane & 7;
    const uint32_t vLane = headBase + 5120u * 2u +
        (uint32_t)(((grp & 1) * 8 + l8) * 40 + (grp >> 1) * 8) * 2u;

#pragma unroll
    for (int kk = 0; kk < 4; ++kk) {
        uint32_t a[4][4];
#pragma unroll
        for (int mt = 0; mt < 4; ++mt)
            LDSM_X4(a[mt][0], a[mt][1], a[mt][2], a[mt][3],
                    pBase + (uint32_t)(mt * 16 * 72 + kk * 16) * 2u);
#pragma unroll
        for (int np = 0; np < 2; ++np) {
            uint32_t r0, r1, r2, r3;
            LDSM_X4_TRANS(r0, r1, r2, r3,
                          vLane + (uint32_t)(kk * 16 * 40 + np * 16) * 2u);
#pragma unroll
            for (int mt = 0; mt < 4; ++mt) {
                mma_f16(accO[mt][np * 2 + 0], a[mt], r0, r1);
                mma_f16(accO[mt][np * 2 + 1], a[mt], r2, r3);
            }
        }
    }

    // store O fp16: unpartition + roll(-4,-4), pixel-major
#pragma unroll
    for (int mt = 0; mt < 4; ++mt) {
#pragma unroll
        for (int e = 0; e < 2; ++e) {
            int tok = mt * 16 + e * 8 + g;
            int hs = ((wl >> 5) << 3) + (tok >> 3);
            int ws = ((wl & 31) << 3) + (tok & 7);
            int h = (hs + 252) & 255;
            int w = (ws + 252) & 255;
            __half* dst = g_o + (((size_t)b * IMG + h) * IMG + w) * DIM + wid * HD;
#pragma unroll
            for (int nt = 0; nt < 4; ++nt) {
                uint32_t p = pack_h2(accO[mt][nt][e * 2], accO[mt][nt][e * 2 + 1]);
                *(uint32_t*)(dst + nt * 8 + 2 * tig) = p;
            }
        }
    }
}

// ---------------------------------------------------------------------------
// fp16 mma.sync proj GEMM (unchanged, at mma.sync HMMA floor):
// CTA tile 64x256, 256 thr (8 warps: 2m x 4n, warp tile 32x64), 2 CTAs/SM,
// 3-stage cp.async, ldmatrix frags. fp32 bias epilogue, row-major store.
// ---------------------------------------------------------------------------
__global__ __launch_bounds__(256, 2)
void proj_gemm(const __half* __restrict__ A16, const __half* __restrict__ Bw,
               const float* __restrict__ bias, float* __restrict__ C) {
    __half* sA = (__half*)dynsmem;          // [3][64][40] halves
    __half* sB = sA + 3 * 2560;             // [3][256][40] halves
    const uint32_t sA_u = smem_u32(sA);
    const uint32_t sB_u = smem_u32(sB);

    const int tid = threadIdx.x;
    const int wid = tid >> 5, lane = tid & 31;
    const int g = lane >> 2, tig = lane & 3;
    const int warp_m = wid & 1, warp_n = wid >> 1;
    const int m0 = blockIdx.y * 64, n0 = blockIdx.x * 256;

    float acc[2][8][4];
#pragma unroll
    for (int i = 0; i < 2; ++i)
#pragma unroll
        for (int j = 0; j < 8; ++j)
#pragma unroll
            for (int c = 0; c < 4; ++c) acc[i][j][c] = 0.f;

    const int arow = tid >> 2, apart = tid & 3;
    auto issue = [&](int s) {
        const int k0 = s * 32;
        const int buf = s % 3;
        CP_ASYNC16(sA_u + (uint32_t)(buf * 2560 + arow * 40 + apart * 8) * 2u,
                   A16 + (size_t)(m0 + arow) * DIM + k0 + apart * 8);
#pragma unroll
        for (int j = 0; j < 4; ++j) {
            int c = tid + j * 256;
            int row = c >> 2, part = c & 3;
            CP_ASYNC16(sB_u + (uint32_t)(buf * 10240 + row * 40 + part * 8) * 2u,
                       Bw + (size_t)(n0 + row) * DIM + k0 + part * 8);
        }
        CP_COMMIT();
    };

    issue(0);
    issue(1);

    const uint32_t a_lane_off = (uint32_t)((lane & 15) * 40 + (lane >> 4) * 8) * 2u;
    const uint32_t b_lane_off = (uint32_t)(lane * 40) * 2u;

#pragma unroll 1
    for (int s = 0; s < 8; ++s) {
        CP_WAIT(1);
        __syncthreads();
        if (s < 6) issue(s + 2);

        const int buf = s % 3;
        const uint32_t aBase =
            sA_u + (uint32_t)(buf * 2560 + warp_m * 32 * 40) * 2u + a_lane_off;
        const uint32_t bBase =
            sB_u + (uint32_t)(buf * 10240 + warp_n * 64 * 40) * 2u + b_lane_off;
#pragma unroll
        for (int kk = 0; kk < 2; ++kk) {
            uint32_t a[2][4];
#pragma unroll
            for (int mt = 0; mt < 2; ++mt)
                LDSM_X4(a[mt][0], a[mt][1], a[mt][2], a[mt][3],
                        aBase + (uint32_t)(mt * 16 * 40 + kk * 16) * 2u);
            uint32_t b0[8], b1[8];
#pragma unroll
            for (int half = 0; half < 2; ++half) {
                const uint32_t hb = bBase + (uint32_t)(half * 32 * 40) * 2u;
                LDSM_X4(b0[half * 4 + 0], b0[half * 4 + 1], b0[half * 4 + 2],
                        b0[half * 4 + 3], hb + (uint32_t)(kk * 16) * 2u);
                LDSM_X4(b1[half * 4 + 0], b1[half * 4 + 1], b1[half * 4 + 2],
                        b1[half * 4 + 3], hb + (uint32_t)(kk * 16 + 8) * 2u);
            }
#pragma unroll
            for (int nt = 0; nt < 8; ++nt)
#pragma unroll
                for (int mt = 0; mt < 2; ++mt)
                    mma_f16(acc[mt][nt], a[mt], b0[nt], b1[nt]);
        }
    }

#pragma unroll
    for (int mt = 0; mt < 2; ++mt) {
#pragma unroll
        for (int e = 0; e < 2; ++e) {
            int row = m0 + warp_m * 32 + mt * 16 + e * 8 + g;
            float* dst = C + (size_t)row * DIM;
#pragma unroll
            for (int nt = 0; nt < 8; ++nt) {
                int col = warp_n * 64 + nt * 8 + 2 * tig;
                float2 bi = *(const float2*)(bias + col);
                float2 v = make_float2(acc[mt][nt][e * 2] + bi.x,
                                       acc[mt][nt][e * 2 + 1] + bi.y);
                *(float2*)(dst + col) = v;
            }
        }
    }
}

// ---------------------------------------------------------------------------

extern "C" void kernel_launch(void* const* d_in, const int* in_sizes, int n_in,
                              void* d_out, int out_size) {
    const float* x      = (const float*)d_in[0];
    const float* qkv_w  = (const float*)d_in[1];
    const float* proj_w = (const float*)d_in[2];
    const float* proj_b = (const float*)d_in[3];
    float* out = (float*)d_out;

    __half* o_ptr = nullptr;
    __half* wq_ptr = nullptr;
    __half* wp_ptr = nullptr;
    cudaGetSymbolAddress((void**)&o_ptr, g_o);
    cudaGetSymbolAddress((void**)&wq_ptr, g_wq);
    cudaGetSymbolAddress((void**)&wp_ptr, g_wp);

    const int fused_smem = 112640 * 2;              // 225280 B
    const int gemm_smem = 3 * (2560 + 10240) * 2;   // 76800 B
    cudaFuncSetAttribute(fused_qkv_attn, cudaFuncAttributeMaxDynamicSharedMemorySize,
                         fused_smem);
    cudaFuncSetAttribute(proj_gemm, cudaFuncAttributeMaxDynamicSharedMemorySize,
                         gemm_smem);

    // 0) fp16-round the weights
    round_kernel<<<196608 / 8 / 256, 256>>>((const float4*)qkv_w, (uint4*)wq_ptr,
                                            196608 / 8);
    round_kernel<<<65536 / 8 / 256, 256>>>((const float4*)proj_w, (uint4*)wp_ptr,
                                           65536 / 8);

    // 1) fused qkv projection + shifted-window attention (no g_qkv round-trip)
    fused_qkv_attn<<<BATCH * NWIN, 256, fused_smem>>>(x, wq_ptr);

    // 2) output projection (fp16 mma) + bias, fp32 out
    proj_gemm<<<dim3(1, NPIX / 64), 256, gemm_smem>>>(o_ptr, wp_ptr, proj_b, out);
}